// round 14
// baseline (speedup 1.0000x reference)
#include <cuda_runtime.h>
#include <math.h>

// Problem constants
#define SS   2048
#define HH   16
#define DD   64
#define EE   1024
#define HB   204          // heavy budget = int(0.1*2048)
#define RB   204          // recent budget
#define CB   408          // cache budget = HB+RB
#define ACTN 409          // active columns per scan step = HB + (RB+1)
#define PEN  0.99f

// Scratch (static __device__ arrays; no allocations allowed)
__device__ float g_q[HH * SS * DD];              // 8.4 MB, head-major [h][s][d], pre-scaled by D^-0.5
__device__ float g_k[HH * SS * DD];
__device__ float g_v[HH * SS * DD];
__device__ float g_probs0[HH * CB * CB];         // causal softmax probs for rows < cb
__device__ float g_acc[HH * SS];                 // initial accumulated attention
__device__ float g_ctx[SS * EE];                 // context [s][h*64+d] before output projection

// ---------------------------------------------------------------------------
// fp32 GEMM: out[m][n] = scale * (sum_k A[m][k] * W[n][k] + bias[n])
// mode 0: write Cout[m*N+n]
// mode 1/2/3: write head-major g_q/g_k/g_v:  dst[((n>>6)*M + m)*64 + (n&63)]
// A == nullptr means "use g_ctx as A"
// 128x128 tile, 256 threads, 8x8 micro-tile, K-step 8.
// ---------------------------------------------------------------------------
__global__ void __launch_bounds__(256) gemm_kernel(
    const float* __restrict__ A, const float* __restrict__ W,
    const float* __restrict__ bias, float* __restrict__ Cout,
    int M, int N, int K, float scale, int mode)
{
    __shared__ float As[8][128];
    __shared__ float Ws[8][128];

    if (A == nullptr) A = g_ctx;

    int tid = threadIdx.x;
    int tx = tid & 15, ty = tid >> 4;
    int m0 = blockIdx.x * 128, n0 = blockIdx.y * 128;
    int lr = tid >> 1, lq = (tid & 1) << 2;

    const float* Ag = A + (size_t)(m0 + lr) * K + lq;
    const float* Wg = W + (size_t)(n0 + lr) * K + lq;

    float acc[8][8];
#pragma unroll
    for (int i = 0; i < 8; i++)
#pragma unroll
        for (int j = 0; j < 8; j++) acc[i][j] = 0.f;

    for (int k0 = 0; k0 < K; k0 += 8) {
        float4 av = *(const float4*)(Ag + k0);
        float4 wv = *(const float4*)(Wg + k0);
        As[lq + 0][lr] = av.x; As[lq + 1][lr] = av.y;
        As[lq + 2][lr] = av.z; As[lq + 3][lr] = av.w;
        Ws[lq + 0][lr] = wv.x; Ws[lq + 1][lr] = wv.y;
        Ws[lq + 2][lr] = wv.z; Ws[lq + 3][lr] = wv.w;
        __syncthreads();
#pragma unroll
        for (int kk = 0; kk < 8; kk++) {
            float a[8], b[8];
            *(float4*)(a)     = *(const float4*)(&As[kk][ty * 8]);
            *(float4*)(a + 4) = *(const float4*)(&As[kk][ty * 8 + 4]);
            *(float4*)(b)     = *(const float4*)(&Ws[kk][tx * 8]);
            *(float4*)(b + 4) = *(const float4*)(&Ws[kk][tx * 8 + 4]);
#pragma unroll
            for (int i = 0; i < 8; i++)
#pragma unroll
                for (int j = 0; j < 8; j++) acc[i][j] += a[i] * b[j];
        }
        __syncthreads();
    }

#pragma unroll
    for (int i = 0; i < 8; i++) {
        int m = m0 + ty * 8 + i;
#pragma unroll
        for (int j = 0; j < 8; j++) {
            int n = n0 + tx * 8 + j;
            float v = scale * (acc[i][j] + bias[n]);
            if (mode == 0) {
                Cout[(size_t)m * N + n] = v;
            } else {
                float* dst = (mode == 1) ? g_q : (mode == 2) ? g_k : g_v;
                dst[((size_t)(n >> 6) * M + m) * 64 + (n & 63)] = v;
            }
        }
    }
}

// ---------------------------------------------------------------------------
// Block reductions (broadcast result to all threads)
// ---------------------------------------------------------------------------
__device__ __forceinline__ float blk_max(float v, float* red, int nwarp) {
    int lane = threadIdx.x & 31, w = threadIdx.x >> 5;
#pragma unroll
    for (int o = 16; o > 0; o >>= 1)
        v = fmaxf(v, __shfl_xor_sync(0xffffffffu, v, o));
    if (lane == 0) red[w] = v;
    __syncthreads();
    if (threadIdx.x == 0) {
        float m = red[0];
        for (int i = 1; i < nwarp; i++) m = fmaxf(m, red[i]);
        red[0] = m;
    }
    __syncthreads();
    float r = red[0];
    __syncthreads();
    return r;
}

__device__ __forceinline__ float blk_sum(float v, float* red, int nwarp) {
    int lane = threadIdx.x & 31, w = threadIdx.x >> 5;
#pragma unroll
    for (int o = 16; o > 0; o >>= 1)
        v += __shfl_xor_sync(0xffffffffu, v, o);
    if (lane == 0) red[w] = v;
    __syncthreads();
    if (threadIdx.x == 0) {
        float s = red[0];
        for (int i = 1; i < nwarp; i++) s += red[i];
        red[0] = s;
    }
    __syncthreads();
    float r = red[0];
    __syncthreads();
    return r;
}

// ---------------------------------------------------------------------------
// Rows 0..CB-1: plain causal softmax. Store probs (for acc init) and emit
// the context rows (these rows' final mask is all-true + tril).
// grid (CB, HH), 256 threads
// ---------------------------------------------------------------------------
__global__ void __launch_bounds__(256) attn_block_kernel()
{
    int t = blockIdx.x, h = blockIdx.y;
    __shared__ float qr[64];
    __shared__ float psm[CB];
    __shared__ float red[16];
    __shared__ float op[4][64];
    int tid = threadIdx.x;

    if (tid < 16)
        ((float4*)qr)[tid] = ((const float4*)(g_q + ((size_t)h * SS + t) * DD))[tid];
    __syncthreads();

    const float4* qv = (const float4*)qr;
    float a0 = -INFINITY, a1 = -INFINITY;
    if (tid <= t) {
        const float4* kr = (const float4*)(g_k + ((size_t)h * SS + tid) * DD);
        float s0 = 0, s1 = 0, s2 = 0, s3 = 0;
#pragma unroll
        for (int i = 0; i < 16; i++) {
            float4 kk = kr[i]; float4 q4 = qv[i];
            s0 += q4.x * kk.x; s1 += q4.y * kk.y; s2 += q4.z * kk.z; s3 += q4.w * kk.w;
        }
        a0 = (s0 + s1) + (s2 + s3);
    }
    int sB = tid + 256;
    if (sB <= t) {
        const float4* kr = (const float4*)(g_k + ((size_t)h * SS + sB) * DD);
        float s0 = 0, s1 = 0, s2 = 0, s3 = 0;
#pragma unroll
        for (int i = 0; i < 16; i++) {
            float4 kk = kr[i]; float4 q4 = qv[i];
            s0 += q4.x * kk.x; s1 += q4.y * kk.y; s2 += q4.z * kk.z; s3 += q4.w * kk.w;
        }
        a1 = (s0 + s1) + (s2 + s3);
    }

    float m = blk_max(fmaxf(a0, a1), red, 8);
    float e0 = (tid <= t) ? expf(a0 - m) : 0.f;
    float e1 = (sB  <= t) ? expf(a1 - m) : 0.f;
    float Z = blk_sum(e0 + e1, red, 8);

    if (tid <= t) {
        float p = e0 / Z;
        psm[tid] = p;
        g_probs0[((size_t)h * CB + t) * CB + tid] = p;
    }
    if (sB <= t) {
        float p = e1 / Z;
        psm[sB] = p;
        g_probs0[((size_t)h * CB + t) * CB + sB] = p;
    }
    __syncthreads();

    int d = tid & 63, ch = tid >> 6;
    float o = 0.f;
    for (int s = ch; s <= t; s += 4)
        o += psm[s] * g_v[((size_t)h * SS + s) * DD + d];
    op[ch][d] = o;
    __syncthreads();
    if (tid < 64) {
        float r = op[0][tid] + op[1][tid] + op[2][tid] + op[3][tid];
        g_ctx[(size_t)t * EE + h * DD + tid] = r;
    }
}

// ---------------------------------------------------------------------------
// acc[h][s] = sum_{t=s}^{CB-1} probs0[h][t][s] * 0.99^(CB-1-t), s < CB; else 0.
// Deterministic fixed-order sum (no atomics). grid HH, 512 threads.
// ---------------------------------------------------------------------------
__global__ void __launch_bounds__(512) acc_init_kernel()
{
    int h = blockIdx.x, tid = threadIdx.x;
    if (tid < CB) {
        float a = 0.f;
        for (int t = tid; t < CB; t++)
            a += g_probs0[((size_t)h * CB + t) * CB + tid] * powf(PEN, (float)(CB - 1 - t));
        g_acc[h * SS + tid] = a;
    }
    for (int i = tid; i < SS; i += blockDim.x)
        if (i >= CB) g_acc[h * SS + i] = 0.f;
}

// ---------------------------------------------------------------------------
// The sequential heavy-hitter scan. One CTA per head, 512 threads.
// Per step tok (CB..SS-1):
//   selection (tok>CB): drop min over {acc[heavy[0..203]], acc[entrant]},
//                       tie -> drop larger column (matches lax.top_k stability);
//                       zero its acc; replace slot with entrant.
//   active cols = heavy[0..203] U [li, tok]  (409 cols, li = tok-RB)
//   p = softmax(q[tok]·k[active]); acc = acc*0.99 (all) + p (active);
//   ctx[tok] = p @ V   (p IS the final attention row for this tok).
// ---------------------------------------------------------------------------
__global__ void __launch_bounds__(512) scan_kernel()
{
    int h = blockIdx.x, tid = threadIdx.x;
    int lane = tid & 31, w = tid >> 5;

    __shared__ float acc[SS];
    __shared__ int   heavy[HB];
    __shared__ float p_act[512];
    __shared__ int   col_act[512];
    __shared__ float qr[64];
    __shared__ float redf[16];
    __shared__ int   redc[16];
    __shared__ int   redslot[16];
    __shared__ float op[8][64];

    for (int i = tid; i < SS; i += 512) acc[i] = g_acc[h * SS + i];
    if (tid < HB) heavy[tid] = tid;
    __syncthreads();

    const float* Kh = g_k + (size_t)h * SS * DD;
    const float* Vh = g_v + (size_t)h * SS * DD;
    const float* Qh = g_q + (size_t)h * SS * DD;

    for (int tok = CB; tok < SS; tok++) {
        int li = tok - RB;

        // --- selection (skip at the very first step: 204 candidates, keep all)
        if (tok > CB) {
            int ecol = tok - RB - 1;   // entrant column (li-1)
            float v; int c, slot;
            if (tid < HB)       { slot = tid; c = heavy[tid]; v = acc[c]; }
            else if (tid == HB) { slot = HB;  c = ecol;       v = acc[ecol]; }
            else                { slot = -1;  c = -1;         v = INFINITY; }
#pragma unroll
            for (int o = 16; o > 0; o >>= 1) {
                float ov = __shfl_xor_sync(0xffffffffu, v, o);
                int   oc = __shfl_xor_sync(0xffffffffu, c, o);
                int   os = __shfl_xor_sync(0xffffffffu, slot, o);
                if (ov < v || (ov == v && oc > c)) { v = ov; c = oc; slot = os; }
            }
            if (lane == 0) { redf[w] = v; redc[w] = c; redslot[w] = slot; }
            __syncthreads();
            if (tid == 0) {
                float bv = redf[0]; int bc = redc[0], bs = redslot[0];
                for (int i = 1; i < 16; i++) {
                    if (redf[i] < bv || (redf[i] == bv && redc[i] > bc)) {
                        bv = redf[i]; bc = redc[i]; bs = redslot[i];
                    }
                }
                acc[bc] = 0.f;                 // dropped column
                if (bs < HB) heavy[bs] = ecol; // entrant survives -> takes the slot
            }
            __syncthreads();
        }

        // --- q row
        if (tid < 16)
            ((float4*)qr)[tid] = ((const float4*)(Qh + (size_t)tok * DD))[tid];
        __syncthreads();

        // --- scores at active columns
        float a = -INFINITY; int c = -1;
        if (tid < ACTN) {
            c = (tid < HB) ? heavy[tid] : (li + tid - HB);
            const float4* kr = (const float4*)(Kh + (size_t)c * DD);
            const float4* qv = (const float4*)qr;
            float s0 = 0, s1 = 0, s2 = 0, s3 = 0;
#pragma unroll
            for (int i = 0; i < 16; i++) {
                float4 kk = kr[i]; float4 q4 = qv[i];
                s0 += q4.x * kk.x; s1 += q4.y * kk.y; s2 += q4.z * kk.z; s3 += q4.w * kk.w;
            }
            a = (s0 + s1) + (s2 + s3);
        }
        col_act[tid] = c;

        float m = blk_max(a, redf, 16);
        float ev = (tid < ACTN) ? expf(a - m) : 0.f;
        float Z = blk_sum(ev, redf, 16);
        float p = ev / Z;
        p_act[tid] = p;
        __syncthreads();

        // --- acc = acc * penalty + p
        for (int i = tid; i < SS; i += 512) acc[i] *= PEN;
        __syncthreads();
        if (tid < ACTN) acc[c] += p;

        // --- emit output row: ctx[tok] = p @ V over active columns
        int d = tid & 63, ch = tid >> 6;
        float o = 0.f;
        for (int j = ch; j < ACTN; j += 8)
            o += p_act[j] * Vh[(size_t)col_act[j] * DD + d];
        op[ch][d] = o;
        __syncthreads();
        if (tid < 64) {
            float r = 0.f;
#pragma unroll
            for (int j = 0; j < 8; j++) r += op[j][tid];
            g_ctx[(size_t)tok * EE + h * DD + tid] = r;
        }
        __syncthreads();
    }
}

// ---------------------------------------------------------------------------
extern "C" void kernel_launch(void* const* d_in, const int* in_sizes, int n_in,
                              void* d_out, int out_size)
{
    (void)in_sizes; (void)n_in; (void)out_size;
    const float* hs = (const float*)d_in[0];
    // d_in[1] = attention_mask: known-causal (0 / float-min); applied analytically.
    const float* Wq = (const float*)d_in[2];
    const float* bq = (const float*)d_in[3];
    const float* Wk = (const float*)d_in[4];
    const float* bk = (const float*)d_in[5];
    const float* Wv = (const float*)d_in[6];
    const float* bv = (const float*)d_in[7];
    const float* Wo = (const float*)d_in[8];
    const float* bo = (const float*)d_in[9];
    float* out = (float*)d_out;

    dim3 ggrid(SS / 128, EE / 128);

    // QKV projections (q pre-scaled by D^-0.5 = 0.125), head-major outputs
    gemm_kernel<<<ggrid, 256>>>(hs, Wq, bq, nullptr, SS, EE, EE, 0.125f, 1);
    gemm_kernel<<<ggrid, 256>>>(hs, Wk, bk, nullptr, SS, EE, EE, 1.0f,   2);
    gemm_kernel<<<ggrid, 256>>>(hs, Wv, bv, nullptr, SS, EE, EE, 1.0f,   3);

    // rows < cb: causal softmax probs + context rows
    attn_block_kernel<<<dim3(CB, HH), 256>>>();

    // penalty-weighted accumulated attention init
    acc_init_kernel<<<HH, 512>>>();

    // sequential heavy-hitter scan, emits context rows cb..S-1
    scan_kernel<<<HH, 512>>>();

    // output projection
    gemm_kernel<<<ggrid, 256>>>(nullptr, Wo, bo, out, SS, EE, EE, 1.0f, 0);
}

// round 17
// speedup vs baseline: 1.8574x; 1.8574x over previous
#include <cuda_runtime.h>
#include <math.h>

// Problem constants
#define SS   2048
#define HH   16
#define DD   64
#define EE   1024
#define HB   204          // heavy budget
#define RB   204          // recent budget
#define CB   408          // cache budget
#define ACTN 409          // active columns per scan step
#define PEN  0.99f
#define MROWS (SS - CB)   // 1640 scan rows

// Scratch (static __device__ arrays; no allocations allowed)
__device__ float g_q[HH * SS * DD];               // head-major [h][s][d], pre-scaled by D^-0.5
__device__ float g_k[HH * SS * DD];
__device__ float g_v[HH * SS * DD];
__device__ float g_sc[(size_t)HH * MROWS * SS];   // precomputed scores rows CB..SS-1 (215MB)
__device__ float g_probs0[HH * CB * CB];          // causal softmax probs for rows < cb
__device__ float g_acc[HH * SS];                  // initial accumulated attention
__device__ float g_ctx[SS * EE];                  // context before output projection

// ---------------------------------------------------------------------------
// fp32 GEMM: out[m][n] = scale * (sum_k A[m][k] * W[n][k] + bias[n])
// mode 0: write Cout[m*N+n]
// mode 1/2/3: write head-major g_q/g_k/g_v
// A == nullptr means "use g_ctx as A"
// ---------------------------------------------------------------------------
__global__ void __launch_bounds__(256) gemm_kernel(
    const float* __restrict__ A, const float* __restrict__ W,
    const float* __restrict__ bias, float* __restrict__ Cout,
    int M, int N, int K, float scale, int mode)
{
    __shared__ float As[8][128];
    __shared__ float Ws[8][128];

    if (A == nullptr) A = g_ctx;

    int tid = threadIdx.x;
    int tx = tid & 15, ty = tid >> 4;
    int m0 = blockIdx.x * 128, n0 = blockIdx.y * 128;
    int lr = tid >> 1, lq = (tid & 1) << 2;

    const float* Ag = A + (size_t)(m0 + lr) * K + lq;
    const float* Wg = W + (size_t)(n0 + lr) * K + lq;

    float acc[8][8];
#pragma unroll
    for (int i = 0; i < 8; i++)
#pragma unroll
        for (int j = 0; j < 8; j++) acc[i][j] = 0.f;

    for (int k0 = 0; k0 < K; k0 += 8) {
        float4 av = *(const float4*)(Ag + k0);
        float4 wv = *(const float4*)(Wg + k0);
        As[lq + 0][lr] = av.x; As[lq + 1][lr] = av.y;
        As[lq + 2][lr] = av.z; As[lq + 3][lr] = av.w;
        Ws[lq + 0][lr] = wv.x; Ws[lq + 1][lr] = wv.y;
        Ws[lq + 2][lr] = wv.z; Ws[lq + 3][lr] = wv.w;
        __syncthreads();
#pragma unroll
        for (int kk = 0; kk < 8; kk++) {
            float a[8], b[8];
            *(float4*)(a)     = *(const float4*)(&As[kk][ty * 8]);
            *(float4*)(a + 4) = *(const float4*)(&As[kk][ty * 8 + 4]);
            *(float4*)(b)     = *(const float4*)(&Ws[kk][tx * 8]);
            *(float4*)(b + 4) = *(const float4*)(&Ws[kk][tx * 8 + 4]);
#pragma unroll
            for (int i = 0; i < 8; i++)
#pragma unroll
                for (int j = 0; j < 8; j++) acc[i][j] += a[i] * b[j];
        }
        __syncthreads();
    }

#pragma unroll
    for (int i = 0; i < 8; i++) {
        int m = m0 + ty * 8 + i;
#pragma unroll
        for (int j = 0; j < 8; j++) {
            int n = n0 + tx * 8 + j;
            float v = scale * (acc[i][j] + bias[n]);
            if (mode == 0) {
                Cout[(size_t)m * N + n] = v;
            } else {
                size_t di = ((size_t)(n >> 6) * M + m) * 64 + (n & 63);
                float* dst = (mode == 1) ? g_q : (mode == 2) ? g_k : g_v;
                dst[di] = v;
            }
        }
    }
}

// ---------------------------------------------------------------------------
// Batched score GEMM: g_sc[h][t-CB][c] = q[h][t] . k[h][c], t in [CB,SS), all c.
// grid (13, 16, HH), block 256. 128x128 tile, K=64.
// ---------------------------------------------------------------------------
__global__ void __launch_bounds__(256) qk_score_kernel()
{
    __shared__ float As[8][128];
    __shared__ float Ws[8][128];

    int tid = threadIdx.x;
    int tx = tid & 15, ty = tid >> 4;
    int h = blockIdx.z;
    int t0 = CB + blockIdx.x * 128;
    int c0 = blockIdx.y * 128;
    int lr = tid >> 1, lq = (tid & 1) << 2;

    int ta = t0 + lr; if (ta >= SS) ta = SS - 1;   // clamp (store is guarded)
    const float* Ag = g_q + ((size_t)h * SS + ta) * DD + lq;
    const float* Wg = g_k + ((size_t)h * SS + c0 + lr) * DD + lq;

    float acc[8][8];
#pragma unroll
    for (int i = 0; i < 8; i++)
#pragma unroll
        for (int j = 0; j < 8; j++) acc[i][j] = 0.f;

#pragma unroll
    for (int k0 = 0; k0 < DD; k0 += 8) {
        float4 av = *(const float4*)(Ag + k0);
        float4 wv = *(const float4*)(Wg + k0);
        As[lq + 0][lr] = av.x; As[lq + 1][lr] = av.y;
        As[lq + 2][lr] = av.z; As[lq + 3][lr] = av.w;
        Ws[lq + 0][lr] = wv.x; Ws[lq + 1][lr] = wv.y;
        Ws[lq + 2][lr] = wv.z; Ws[lq + 3][lr] = wv.w;
        __syncthreads();
#pragma unroll
        for (int kk = 0; kk < 8; kk++) {
            float a[8], b[8];
            *(float4*)(a)     = *(const float4*)(&As[kk][ty * 8]);
            *(float4*)(a + 4) = *(const float4*)(&As[kk][ty * 8 + 4]);
            *(float4*)(b)     = *(const float4*)(&Ws[kk][tx * 8]);
            *(float4*)(b + 4) = *(const float4*)(&Ws[kk][tx * 8 + 4]);
#pragma unroll
            for (int i = 0; i < 8; i++)
#pragma unroll
                for (int j = 0; j < 8; j++) acc[i][j] += a[i] * b[j];
        }
        __syncthreads();
    }

#pragma unroll
    for (int i = 0; i < 8; i++) {
        int t = t0 + ty * 8 + i;
        if (t < SS) {
#pragma unroll
            for (int j = 0; j < 8; j++) {
                int c = c0 + tx * 8 + j;
                g_sc[((size_t)h * MROWS + (t - CB)) * SS + c] = acc[i][j];
            }
        }
    }
}

// ---------------------------------------------------------------------------
// Block reductions for attn_block
// ---------------------------------------------------------------------------
__device__ __forceinline__ float blk_max(float v, float* red, int nwarp) {
    int lane = threadIdx.x & 31, w = threadIdx.x >> 5;
#pragma unroll
    for (int o = 16; o > 0; o >>= 1)
        v = fmaxf(v, __shfl_xor_sync(0xffffffffu, v, o));
    if (lane == 0) red[w] = v;
    __syncthreads();
    if (threadIdx.x == 0) {
        float m = red[0];
        for (int i = 1; i < nwarp; i++) m = fmaxf(m, red[i]);
        red[0] = m;
    }
    __syncthreads();
    float r = red[0];
    __syncthreads();
    return r;
}

__device__ __forceinline__ float blk_sum(float v, float* red, int nwarp) {
    int lane = threadIdx.x & 31, w = threadIdx.x >> 5;
#pragma unroll
    for (int o = 16; o > 0; o >>= 1)
        v += __shfl_xor_sync(0xffffffffu, v, o);
    if (lane == 0) red[w] = v;
    __syncthreads();
    if (threadIdx.x == 0) {
        float s = red[0];
        for (int i = 1; i < nwarp; i++) s += red[i];
        red[0] = s;
    }
    __syncthreads();
    float r = red[0];
    __syncthreads();
    return r;
}

// ---------------------------------------------------------------------------
// Rows 0..CB-1: plain causal softmax + context. grid (CB, HH), 256 threads.
// ---------------------------------------------------------------------------
__global__ void __launch_bounds__(256) attn_block_kernel()
{
    int t = blockIdx.x, h = blockIdx.y;
    __shared__ float qr[64];
    __shared__ float psm[CB];
    __shared__ float red[16];
    __shared__ float op[4][64];
    int tid = threadIdx.x;

    if (tid < 16)
        ((float4*)qr)[tid] = ((const float4*)(g_q + ((size_t)h * SS + t) * DD))[tid];
    __syncthreads();

    const float4* qv = (const float4*)qr;
    float a0 = -INFINITY, a1 = -INFINITY;
    if (tid <= t) {
        const float4* kr = (const float4*)(g_k + ((size_t)h * SS + tid) * DD);
        float s0 = 0, s1 = 0, s2 = 0, s3 = 0;
#pragma unroll
        for (int i = 0; i < 16; i++) {
            float4 kk = kr[i]; float4 q4 = qv[i];
            s0 += q4.x * kk.x; s1 += q4.y * kk.y; s2 += q4.z * kk.z; s3 += q4.w * kk.w;
        }
        a0 = (s0 + s1) + (s2 + s3);
    }
    int sB = tid + 256;
    if (sB <= t) {
        const float4* kr = (const float4*)(g_k + ((size_t)h * SS + sB) * DD);
        float s0 = 0, s1 = 0, s2 = 0, s3 = 0;
#pragma unroll
        for (int i = 0; i < 16; i++) {
            float4 kk = kr[i]; float4 q4 = qv[i];
            s0 += q4.x * kk.x; s1 += q4.y * kk.y; s2 += q4.z * kk.z; s3 += q4.w * kk.w;
        }
        a1 = (s0 + s1) + (s2 + s3);
    }

    float m = blk_max(fmaxf(a0, a1), red, 8);
    float e0 = (tid <= t) ? expf(a0 - m) : 0.f;
    float e1 = (sB  <= t) ? expf(a1 - m) : 0.f;
    float Z = blk_sum(e0 + e1, red, 8);

    if (tid <= t) {
        float p = e0 / Z;
        psm[tid] = p;
        g_probs0[((size_t)h * CB + t) * CB + tid] = p;
    }
    if (sB <= t) {
        float p = e1 / Z;
        psm[sB] = p;
        g_probs0[((size_t)h * CB + t) * CB + sB] = p;
    }
    __syncthreads();

    int d = tid & 63, ch = tid >> 6;
    float o = 0.f;
    for (int s = ch; s <= t; s += 4)
        o += psm[s] * g_v[((size_t)h * SS + s) * DD + d];
    op[ch][d] = o;
    __syncthreads();
    if (tid < 64) {
        float r = op[0][tid] + op[1][tid] + op[2][tid] + op[3][tid];
        g_ctx[(size_t)t * EE + h * DD + tid] = r;
    }
}

// ---------------------------------------------------------------------------
// acc init: acc[h][s] = sum_{t=s}^{CB-1} probs0[h][t][s] * PEN^(CB-1-t)
// ---------------------------------------------------------------------------
__global__ void __launch_bounds__(512) acc_init_kernel()
{
    int h = blockIdx.x, tid = threadIdx.x;
    if (tid < CB) {
        float a = 0.f;
        for (int t = tid; t < CB; t++)
            a += g_probs0[((size_t)h * CB + t) * CB + tid] * powf(PEN, (float)(CB - 1 - t));
        g_acc[h * SS + tid] = a;
    }
    for (int i = tid; i < SS; i += blockDim.x)
        if (i >= CB) g_acc[h * SS + i] = 0.f;
}

// ---------------------------------------------------------------------------
// Scan: one CTA per head, 512 threads. Scores precomputed (g_sc). V lives in
// SMEM as fp32: ring buffer (recent 256 rows) + heavy-slot array (204 rows).
// NOTE: 8-byte-accessed arrays come FIRST in the struct (alignment!).
// ---------------------------------------------------------------------------
struct alignas(16) ScanSmem {
    float vring[256][64];     // fp32 V rows, slot = col & 255   (float2-accessed)
    float vheavy[HB][64];     // fp32 V rows, by heavy slot      (float2-accessed)
    float acc[SS];
    float p_act[512];
    float op[16][64];
    float m_w[16];
    float s_w[16];
    float redf[16];
    float b_M;
    float b_Z;
    int   heavy[HB];
    int   col_act[512];
    int   redc[16];
    int   redslot[16];
    int   b_bs;
};

__global__ void __launch_bounds__(512) scan_kernel()
{
    extern __shared__ char smem_raw[];
    ScanSmem& S = *reinterpret_cast<ScanSmem*>(smem_raw);

    int h = blockIdx.x, tid = threadIdx.x;
    int lane = tid & 31, w = tid >> 5;

    const float* Vh = g_v + (size_t)h * SS * DD;
    const float* ScH = g_sc + (size_t)h * MROWS * SS;

    for (int i = tid; i < SS; i += 512) S.acc[i] = g_acc[h * SS + i];
    if (tid < HB) S.heavy[tid] = tid;
    for (int idx = tid; idx < HB * DD / 2; idx += 512) {        // heavy slots = rows 0..203
        int r = idx / 32, l = idx & 31;
        *(float2*)&S.vheavy[r][l * 2] = *(const float2*)(Vh + (size_t)r * DD + l * 2);
    }
    for (int idx = tid; idx < (RB + 1) * DD / 2; idx += 512) {  // ring = rows 204..408
        int r = RB + idx / 32, l = idx & 31;
        *(float2*)&S.vring[r & 255][l * 2] = *(const float2*)(Vh + (size_t)r * DD + l * 2);
    }
    __syncthreads();

    for (int tok = CB; tok < SS; tok++) {
        int li = tok - RB;
        int ecol = li - 1;

        // ring insert for this step's newest column (row tok)
        if (w == 15)
            *(float2*)&S.vring[tok & 255][lane * 2] =
                *(const float2*)(Vh + (size_t)tok * DD + lane * 2);

        // --- selection (skip at first step)
        if (tok > CB) {
            float v; int c, slot;
            if (tid < HB)       { slot = tid; c = S.heavy[tid]; v = S.acc[c]; }
            else if (tid == HB) { slot = HB;  c = ecol;         v = S.acc[ecol]; }
            else                { slot = -1;  c = -1;           v = INFINITY; }
#pragma unroll
            for (int o = 16; o > 0; o >>= 1) {
                float ov = __shfl_xor_sync(0xffffffffu, v, o);
                int   oc = __shfl_xor_sync(0xffffffffu, c, o);
                int   os = __shfl_xor_sync(0xffffffffu, slot, o);
                if (ov < v || (ov == v && oc > c)) { v = ov; c = oc; slot = os; }
            }
            if (lane == 0) { S.redf[w] = v; S.redc[w] = c; S.redslot[w] = slot; }
            __syncthreads();
            if (tid == 0) {
                float bv = S.redf[0]; int bc = S.redc[0], bs = S.redslot[0];
                for (int i = 1; i < 16; i++) {
                    if (S.redf[i] < bv || (S.redf[i] == bv && S.redc[i] > bc)) {
                        bv = S.redf[i]; bc = S.redc[i]; bs = S.redslot[i];
                    }
                }
                S.acc[bc] = 0.f;                // dropped column
                if (bs < HB) S.heavy[bs] = ecol;
                S.b_bs = bs;
            }
            __syncthreads();
            // entrant promoted into heavy slot: copy its V row (still in ring)
            if (w == 14 && S.b_bs < HB)
                *(float2*)&S.vheavy[S.b_bs][lane * 2] =
                    *(const float2*)&S.vring[ecol & 255][lane * 2];
        }

        // --- gather scores + one-round online softmax
        const float* sc_row = ScH + (size_t)(tok - CB) * SS;
        float a = -INFINITY; int c = -1;
        if (tid < ACTN) {
            c = (tid < HB) ? S.heavy[tid] : (li + tid - HB);
            a = __ldg(sc_row + c);
        }
        float mw = a;
#pragma unroll
        for (int o = 16; o > 0; o >>= 1)
            mw = fmaxf(mw, __shfl_xor_sync(0xffffffffu, mw, o));
        float ev = (tid < ACTN) ? expf(a - mw) : 0.f;
        float sw = ev;
#pragma unroll
        for (int o = 16; o > 0; o >>= 1)
            sw += __shfl_xor_sync(0xffffffffu, sw, o);
        if (lane == 0) { S.m_w[w] = mw; S.s_w[w] = sw; }
        __syncthreads();
        if (tid == 0) {
            float M = -INFINITY;
            for (int i = 0; i < 16; i++) M = fmaxf(M, S.m_w[i]);
            float Z = 0.f;
            for (int i = 0; i < 16; i++)
                if (S.s_w[i] > 0.f) Z += S.s_w[i] * expf(S.m_w[i] - M);
            S.b_M = M; S.b_Z = Z;
        }
        __syncthreads();
        float p = 0.f;
        if (tid < ACTN) p = ev * expf(S.m_w[w] - S.b_M) / S.b_Z;
        S.p_act[tid] = p;
        S.col_act[tid] = c;

        // --- acc = acc * penalty, then + p at active cols
        for (int i = tid; i < SS; i += 512) S.acc[i] *= PEN;
        __syncthreads();
        if (tid < ACTN) S.acc[c] += p;

        // --- p @ V, all V from SMEM. warp w handles cols j = w, w+16, ...
        float o0 = 0.f, o1 = 0.f;
        for (int j = w; j < ACTN; j += 16) {
            float pj = S.p_act[j];
            float2 f = (j < HB) ? *(const float2*)&S.vheavy[j][lane * 2]
                                : *(const float2*)&S.vring[(li + j - HB) & 255][lane * 2];
            o0 += pj * f.x; o1 += pj * f.y;
        }
        S.op[w][lane * 2]     = o0;
        S.op[w][lane * 2 + 1] = o1;
        __syncthreads();
        if (tid < 64) {
            float r = 0.f;
#pragma unroll
            for (int i = 0; i < 16; i++) r += S.op[i][tid];
            g_ctx[(size_t)tok * EE + h * DD + tid] = r;
        }
        __syncthreads();
    }
}

// ---------------------------------------------------------------------------
extern "C" void kernel_launch(void* const* d_in, const int* in_sizes, int n_in,
                              void* d_out, int out_size)
{
    (void)in_sizes; (void)n_in; (void)out_size;
    const float* hs = (const float*)d_in[0];
    // d_in[1] = attention_mask: known-causal (0 / float-min); applied analytically.
    const float* Wq = (const float*)d_in[2];
    const float* bq = (const float*)d_in[3];
    const float* Wk = (const float*)d_in[4];
    const float* bk = (const float*)d_in[5];
    const float* Wv = (const float*)d_in[6];
    const float* bv = (const float*)d_in[7];
    const float* Wo = (const float*)d_in[8];
    const float* bo = (const float*)d_in[9];
    float* out = (float*)d_out;

    cudaFuncSetAttribute(scan_kernel, cudaFuncAttributeMaxDynamicSharedMemorySize,
                         (int)sizeof(ScanSmem));

    dim3 ggrid(SS / 128, EE / 128);

    // QKV projections (q pre-scaled by D^-0.5), head-major outputs
    gemm_kernel<<<ggrid, 256>>>(hs, Wq, bq, nullptr, SS, EE, EE, 0.125f, 1);
    gemm_kernel<<<ggrid, 256>>>(hs, Wk, bk, nullptr, SS, EE, EE, 1.0f,   2);
    gemm_kernel<<<ggrid, 256>>>(hs, Wv, bv, nullptr, SS, EE, EE, 1.0f,   3);

    // precompute scan-row scores at full chip
    qk_score_kernel<<<dim3(13, 16, HH), 256>>>();

    // rows < cb: causal softmax probs + context rows
    attn_block_kernel<<<dim3(CB, HH), 256>>>();

    // penalty-weighted accumulated attention init
    acc_init_kernel<<<HH, 512>>>();

    // sequential heavy-hitter scan, emits context rows cb..S-1
    scan_kernel<<<HH, 512, sizeof(ScanSmem)>>>();

    // output projection
    gemm_kernel<<<ggrid, 256>>>(nullptr, Wo, bo, out, SS, EE, EE, 1.0f, 0);
}